// round 2
// baseline (speedup 1.0000x reference)
#include <cuda_runtime.h>
#include <cuda_bf16.h>

// Problem constants
#define NROWS 8192           // 2 * 4096
#define HALF  4096
#define DIM   256
#define BM 128
#define BN 128
#define BK 8

// Scratch (allocation-free rule: __device__ globals)
__device__ double g_S1;              // sum of row sumsqs
__device__ float  g_colsum[DIM];     // column sums of total
__device__ float  g_sq[NROWS];       // per-row sumsq
__device__ float  g_negc;            // -log2(e) / (16 * bandwidth)
__device__ double g_acc;             // signed kernel-sum accumulator

__device__ __forceinline__ float ex2f(float x) {
    float y;
    asm("ex2.approx.f32 %0, %1;" : "=f"(y) : "f"(x));
    return y;
}

// ---------------------------------------------------------------------------
// Kernel 0: zero the accumulators (fresh every graph replay)
// ---------------------------------------------------------------------------
__global__ void k0_zero() {
    int tid = threadIdx.x;
    if (tid == 0) g_S1 = 0.0;
    if (tid < DIM) g_colsum[tid] = 0.0f;
}

// ---------------------------------------------------------------------------
// Kernel 1: per-row sumsq + column sums.  One warp per row.
// grid = 1024 blocks x 256 threads (8 warps -> 8 rows per block)
// ---------------------------------------------------------------------------
__global__ void k1_rowstats(const float* __restrict__ src,
                            const float* __restrict__ tgt) {
    __shared__ float cs[DIM];
    __shared__ float s1p[8];
    int tid  = threadIdx.x;
    int warp = tid >> 5;
    int lane = tid & 31;

    cs[tid] = 0.0f;
    __syncthreads();

    int row = blockIdx.x * 8 + warp;
    const float* p = (row < HALF) ? (src + (size_t)row * DIM)
                                  : (tgt + (size_t)(row - HALF) * DIM);
    const float4* p4 = (const float4*)p;
    float4 v0 = p4[lane];        // cols 4*lane .. 4*lane+3
    float4 v1 = p4[lane + 32];   // cols 128+4*lane ..

    float ss = v0.x*v0.x + v0.y*v0.y + v0.z*v0.z + v0.w*v0.w
             + v1.x*v1.x + v1.y*v1.y + v1.z*v1.z + v1.w*v1.w;
    #pragma unroll
    for (int o = 16; o; o >>= 1) ss += __shfl_xor_sync(0xffffffffu, ss, o);
    if (lane == 0) { g_sq[row] = ss; s1p[warp] = ss; }

    int c0 = 4 * lane;
    atomicAdd(&cs[c0 + 0], v0.x); atomicAdd(&cs[c0 + 1], v0.y);
    atomicAdd(&cs[c0 + 2], v0.z); atomicAdd(&cs[c0 + 3], v0.w);
    atomicAdd(&cs[128 + c0 + 0], v1.x); atomicAdd(&cs[128 + c0 + 1], v1.y);
    atomicAdd(&cs[128 + c0 + 2], v1.z); atomicAdd(&cs[128 + c0 + 3], v1.w);
    __syncthreads();

    if (tid == 0) {
        double s = 0.0;
        #pragma unroll
        for (int w = 0; w < 8; w++) s += (double)s1p[w];
        atomicAdd(&g_S1, s);
    }
    atomicAdd(&g_colsum[tid], cs[tid]);
}

// ---------------------------------------------------------------------------
// Kernel 2: bandwidth from the closed form; also resets the main accumulator.
// ---------------------------------------------------------------------------
__global__ void k2_bandwidth() {
    __shared__ float red[DIM];
    int tid = threadIdx.x;
    float c = g_colsum[tid];
    red[tid] = c * c;
    __syncthreads();
    for (int s = 128; s; s >>= 1) {
        if (tid < s) red[tid] += red[tid + s];
        __syncthreads();
    }
    if (tid == 0) {
        const double N = (double)NROWS;
        double sum_l2 = 2.0 * N * g_S1 - 2.0 * (double)red[0];
        double bw = sum_l2 / (N * N - N);
        bw = bw / 4.0;  // KERNEL_MUL^(KERNEL_NUM/2) = 2^2
        g_negc = (float)(-1.4426950408889634 / (16.0 * bw));
        g_acc = 0.0;
    }
}

// ---------------------------------------------------------------------------
// Kernel 3: fused Gram GEMM + RBF-kernel-sum + signed reduction.
// 128x128 tile, 256 threads, 8x8 register blocking, BK=8.
// ---------------------------------------------------------------------------
__global__ __launch_bounds__(256, 2)
void k3_main(const float* __restrict__ src, const float* __restrict__ tgt) {
    __shared__ float As[BK][BM];
    __shared__ float Bs[BK][BN];
    __shared__ float rbuf[256];

    int tid = threadIdx.x;
    int i0 = blockIdx.y * BM;
    int j0 = blockIdx.x * BN;

    // loader mapping: 2 threads per row, each loads one float4 of the BK slice
    int lrow = tid >> 1;
    int lk   = (tid & 1) * 4;
    int arow = i0 + lrow;
    int brow = j0 + lrow;
    const float* ap = ((arow < HALF) ? (src + (size_t)arow * DIM)
                                     : (tgt + (size_t)(arow - HALF) * DIM)) + lk;
    const float* bp = ((brow < HALF) ? (src + (size_t)brow * DIM)
                                     : (tgt + (size_t)(brow - HALF) * DIM)) + lk;

    int tx = tid & 15;   // 16 col-threads
    int ty = tid >> 4;   // 16 row-threads

    float acc[8][8];
    #pragma unroll
    for (int m = 0; m < 8; m++)
        #pragma unroll
        for (int n = 0; n < 8; n++) acc[m][n] = 0.0f;

    for (int k = 0; k < DIM; k += BK) {
        float4 va = *(const float4*)(ap + k);
        float4 vb = *(const float4*)(bp + k);
        __syncthreads();
        As[lk + 0][lrow] = va.x; As[lk + 1][lrow] = va.y;
        As[lk + 2][lrow] = va.z; As[lk + 3][lrow] = va.w;
        Bs[lk + 0][lrow] = vb.x; Bs[lk + 1][lrow] = vb.y;
        Bs[lk + 2][lrow] = vb.z; Bs[lk + 3][lrow] = vb.w;
        __syncthreads();

        #pragma unroll
        for (int kk = 0; kk < BK; kk++) {
            float a[8], b[8];
            *(float4*)(a)     = *(const float4*)&As[kk][ty * 8];
            *(float4*)(a + 4) = *(const float4*)&As[kk][ty * 8 + 4];
            *(float4*)(b)     = *(const float4*)&Bs[kk][tx * 8];
            *(float4*)(b + 4) = *(const float4*)&Bs[kk][tx * 8 + 4];
            #pragma unroll
            for (int m = 0; m < 8; m++)
                #pragma unroll
                for (int n = 0; n < 8; n++)
                    acc[m][n] += a[m] * b[n];
        }
    }

    // Epilogue: l2 -> u = exp(-l2/(16 bw)); kernel sum = u + u^2 + u^4 + u^8 + u^16
    float negc = g_negc;
    float sqi[8], sqj[8];
    #pragma unroll
    for (int m = 0; m < 8; m++) sqi[m] = g_sq[i0 + ty * 8 + m];
    #pragma unroll
    for (int n = 0; n < 8; n++) sqj[n] = g_sq[j0 + tx * 8 + n];

    float tsum = 0.0f;
    #pragma unroll
    for (int m = 0; m < 8; m++) {
        #pragma unroll
        for (int n = 0; n < 8; n++) {
            float l2 = sqi[m] + sqj[n] - 2.0f * acc[m][n];
            float u   = ex2f(l2 * negc);
            float u2  = u * u;
            float u4  = u2 * u2;
            float u8  = u4 * u4;
            float u16 = u8 * u8;
            tsum += ((u + u2) + (u4 + u8)) + u16;
        }
    }

    rbuf[tid] = tsum;
    __syncthreads();
    for (int s = 128; s; s >>= 1) {
        if (tid < s) rbuf[tid] += rbuf[tid + s];
        __syncthreads();
    }
    if (tid == 0) {
        float sign = ((i0 < HALF) == (j0 < HALF)) ? 1.0f : -1.0f;
        atomicAdd(&g_acc, (double)(sign * rbuf[0]));
    }
}

// ---------------------------------------------------------------------------
// Kernel 4: finalize mean
// ---------------------------------------------------------------------------
__global__ void k4_final(float* out) {
    if (threadIdx.x == 0)
        out[0] = (float)(g_acc / ((double)HALF * (double)HALF));
}

extern "C" void kernel_launch(void* const* d_in, const int* in_sizes, int n_in,
                              void* d_out, int out_size) {
    const float* src = (const float*)d_in[0];
    const float* tgt = (const float*)d_in[1];
    float* out = (float*)d_out;

    k0_zero<<<1, 256>>>();
    k1_rowstats<<<NROWS / 8, 256>>>(src, tgt);
    k2_bandwidth<<<1, 256>>>();
    dim3 grid(NROWS / BN, NROWS / BM);
    k3_main<<<grid, 256>>>(src, tgt);
    k4_final<<<1, 32>>>(out);
}

// round 4
// speedup vs baseline: 3.6362x; 3.6362x over previous
#include <cuda_runtime.h>
#include <cuda_bf16.h>
#include <cstdint>

// ---------------- problem constants ----------------
#define NROWS 8192           // 2 * 4096
#define HALF  4096
#define DIM   256
#define KSPLIT 768           // 3 * DIM : A=[hi|hi|lo], B=[hi|lo|hi]
#define BM 128
#define BN 128
#define BKB 64               // bf16 per K chunk (128 bytes per row)
#define KTILES (KSPLIT / BKB) // 12
#define NSTAGE 4
#define NBLK (NROWS / BM)    // 64 row-blocks
#define NTILES (NBLK * (NBLK + 1) / 2)  // 2080 upper-triangle tiles

#define STAGE_BYTES 32768    // A 16KB + B 16KB
#define DSM_BYTES (NSTAGE * STAGE_BYTES)

// ---------------- device scratch ----------------
__device__ double g_S1;
__device__ float  g_colsum[DIM];
__device__ float  g_sq[NROWS];
__device__ float  g_negc;            // -log2(e)/(16*bandwidth)
__device__ double g_acc;
__device__ __align__(16) __nv_bfloat16 g_A[(size_t)NROWS * KSPLIT];
__device__ __align__(16) __nv_bfloat16 g_B[(size_t)NROWS * KSPLIT];

// ---------------- PTX helpers (base-ISA only; no tcgen05 on compute_103) ----
__device__ __forceinline__ float ex2f(float x) {
    float y; asm("ex2.approx.f32 %0, %1;" : "=f"(y) : "f"(x)); return y;
}
__device__ __forceinline__ uint32_t smem_u32(const void* p) {
    uint32_t a;
    asm("{ .reg .u64 t; cvta.to.shared.u64 t, %1; cvt.u32.u64 %0, t; }" : "=r"(a) : "l"(p));
    return a;
}
__device__ __forceinline__ void cp16(uint32_t saddr, const void* g) {
    asm volatile("cp.async.cg.shared.global [%0], [%1], 16;" :: "r"(saddr), "l"(g));
}
#define CP_COMMIT() asm volatile("cp.async.commit_group;" ::: "memory")
#define CP_WAIT2()  asm volatile("cp.async.wait_group 2;" ::: "memory")

__device__ __forceinline__ void ldsm4(uint32_t* r, uint32_t addr) {
    asm volatile("ldmatrix.sync.aligned.m8n8.x4.shared.b16 {%0,%1,%2,%3}, [%4];"
        : "=r"(r[0]), "=r"(r[1]), "=r"(r[2]), "=r"(r[3]) : "r"(addr));
}
__device__ __forceinline__ void mma16816(float* c, const uint32_t* a,
                                         uint32_t b0, uint32_t b1) {
    asm volatile(
        "mma.sync.aligned.m16n8k16.row.col.f32.bf16.bf16.f32 "
        "{%0,%1,%2,%3}, {%4,%5,%6,%7}, {%8,%9}, {%0,%1,%2,%3};"
        : "+f"(c[0]), "+f"(c[1]), "+f"(c[2]), "+f"(c[3])
        : "r"(a[0]), "r"(a[1]), "r"(a[2]), "r"(a[3]), "r"(b0), "r"(b1));
}

// ---------------------------------------------------------------------------
// k0: zero accumulators
// ---------------------------------------------------------------------------
__global__ void k0_zero() {
    int tid = threadIdx.x;
    if (tid == 0) g_S1 = 0.0;
    if (tid < DIM) g_colsum[tid] = 0.0f;
}

// ---------------------------------------------------------------------------
// k1: per-row sumsq + column sums (one warp per row)
// ---------------------------------------------------------------------------
__global__ void k1_rowstats(const float* __restrict__ src,
                            const float* __restrict__ tgt) {
    __shared__ float cs[DIM];
    __shared__ float s1p[8];
    int tid = threadIdx.x, warp = tid >> 5, lane = tid & 31;
    cs[tid] = 0.0f;
    __syncthreads();

    int row = blockIdx.x * 8 + warp;
    const float* p = (row < HALF) ? (src + (size_t)row * DIM)
                                  : (tgt + (size_t)(row - HALF) * DIM);
    const float4* p4 = (const float4*)p;
    float4 v0 = p4[lane];
    float4 v1 = p4[lane + 32];
    float ss = v0.x*v0.x + v0.y*v0.y + v0.z*v0.z + v0.w*v0.w
             + v1.x*v1.x + v1.y*v1.y + v1.z*v1.z + v1.w*v1.w;
    #pragma unroll
    for (int o = 16; o; o >>= 1) ss += __shfl_xor_sync(0xffffffffu, ss, o);
    if (lane == 0) { g_sq[row] = ss; s1p[warp] = ss; }

    int c0 = 4 * lane;
    atomicAdd(&cs[c0 + 0], v0.x); atomicAdd(&cs[c0 + 1], v0.y);
    atomicAdd(&cs[c0 + 2], v0.z); atomicAdd(&cs[c0 + 3], v0.w);
    atomicAdd(&cs[128 + c0 + 0], v1.x); atomicAdd(&cs[128 + c0 + 1], v1.y);
    atomicAdd(&cs[128 + c0 + 2], v1.z); atomicAdd(&cs[128 + c0 + 3], v1.w);
    __syncthreads();

    if (tid == 0) {
        double s = 0.0;
        #pragma unroll
        for (int w = 0; w < 8; w++) s += (double)s1p[w];
        atomicAdd(&g_S1, s);
    }
    atomicAdd(&g_colsum[tid], cs[tid]);
}

// ---------------------------------------------------------------------------
// k1b: hi/lo bf16 split, K-concatenated operands
// ---------------------------------------------------------------------------
__global__ void k1b_convert(const float* __restrict__ src,
                            const float* __restrict__ tgt) {
    int row = blockIdx.x;
    int c = threadIdx.x;                       // 256 threads
    const float* p = (row < HALF) ? (src + (size_t)row * DIM)
                                  : (tgt + (size_t)(row - HALF) * DIM);
    float x = p[c];
    __nv_bfloat16 hi = __float2bfloat16(x);
    __nv_bfloat16 lo = __float2bfloat16(x - __bfloat162float(hi));
    size_t b = (size_t)row * KSPLIT;
    g_A[b + c]       = hi;  g_A[b + DIM + c] = hi;  g_A[b + 2*DIM + c] = lo;
    g_B[b + c]       = hi;  g_B[b + DIM + c] = lo;  g_B[b + 2*DIM + c] = hi;
}

// ---------------------------------------------------------------------------
// k2: bandwidth closed form; reset main accumulator
// ---------------------------------------------------------------------------
__global__ void k2_bandwidth() {
    __shared__ float red[DIM];
    int tid = threadIdx.x;
    float c = g_colsum[tid];
    red[tid] = c * c;
    __syncthreads();
    for (int s = 128; s; s >>= 1) { if (tid < s) red[tid] += red[tid + s]; __syncthreads(); }
    if (tid == 0) {
        const double N = (double)NROWS;
        double sum_l2 = 2.0 * N * g_S1 - 2.0 * (double)red[0];
        double bw = sum_l2 / (N * N - N);
        bw = bw / 4.0;                          // KERNEL_MUL^(KERNEL_NUM//2)
        g_negc = (float)(-1.4426950408889634 / (16.0 * bw));
        g_acc = 0.0;
    }
}

// ---------------------------------------------------------------------------
// k3: block-triangular Gram GEMM via mma.sync bf16 + fused RBF epilogue
//     128x128 tile, 256 thr, warp tile 64x32, 4-stage cp.async pipeline
// ---------------------------------------------------------------------------
__global__ void __launch_bounds__(256, 1) k3_mma() {
    extern __shared__ char dsm[];
    uint32_t smbase = smem_u32(dsm);

    __shared__ float sqic[BM];
    __shared__ float sqjc[BN];
    __shared__ float redw[8];

    int tid = threadIdx.x, wid = tid >> 5, lane = tid & 31;

    // --- map linear block id -> upper-triangle tile (bi, bj), bj >= bi ---
    int t = blockIdx.x;
    int bi = 0;
    #pragma unroll 1
    while (t >= NBLK - bi) { t -= NBLK - bi; bi++; }
    int bj = bi + t;
    int i0 = bi * BM, j0 = bj * BN;

    const __nv_bfloat16* Ag = g_A + (size_t)i0 * KSPLIT;
    const __nv_bfloat16* Bg = g_B + (size_t)j0 * KSPLIT;

    // --- prologue: issue first NSTAGE-1 stages ---
    // loader: per stage, each thread does 4 A-chunks + 4 B-chunks of 16B
    int lrow = tid >> 3;          // used with +32*i
    int lq   = tid & 7;
    uint32_t lo0 = (uint32_t)(lrow * 128 + lq * 16);
    #pragma unroll
    for (int s = 0; s < NSTAGE - 1; s++) {
        uint32_t smA = smbase + s * STAGE_BYTES;
        uint32_t smB = smA + 16384;
        const __nv_bfloat16* ga = Ag + s * BKB + lq * 8;
        const __nv_bfloat16* gb = Bg + s * BKB + lq * 8;
        #pragma unroll
        for (int i = 0; i < 4; i++) {
            uint32_t o = lo0 + (uint32_t)(i * 32 * 128);
            uint32_t sw = o ^ ((o >> 3) & 0x70);
            cp16(smA + sw, ga + (size_t)(lrow + 32 * i) * KSPLIT);
            cp16(smB + sw, gb + (size_t)(lrow + 32 * i) * KSPLIT);
        }
        CP_COMMIT();
    }

    // sq caches (scaled by negc)
    float negc = g_negc;
    if (tid < 128)        sqic[tid]       = g_sq[i0 + tid] * negc;
    else                  sqjc[tid - 128] = g_sq[j0 + tid - 128] * negc;

    // --- warp tiling: 2 (m) x 4 (n) warps; warp tile 64x32 ---
    int wm = wid >> 2;            // 0..1
    int wn = wid & 3;             // 0..3

    // precomputed ldmatrix lane address parts
    // A: tile tm rows = wm*64 + tm*16 + (lane&15); chunk sel = lane&16 (bytes)
    uint32_t arow[4], av[4];
    #pragma unroll
    for (int tm = 0; tm < 4; tm++) {
        uint32_t o = (uint32_t)((wm * 64 + tm * 16 + (lane & 15)) * 128);
        arow[tm] = o;
        av[tm] = (o >> 3) & 0x70;
    }
    // B: group tg rows(n) = wn*32 + tg*16 + (lane&15)
    uint32_t brow[2], bv[2];
    #pragma unroll
    for (int tg = 0; tg < 2; tg++) {
        uint32_t o = (uint32_t)((wn * 32 + tg * 16 + (lane & 15)) * 128);
        brow[tg] = o;
        bv[tg] = (o >> 3) & 0x70;
    }
    uint32_t ksel = (uint32_t)(lane & 16);   // 0 or 16 bytes

    float acc[4][4][4];
    #pragma unroll
    for (int a = 0; a < 4; a++)
        #pragma unroll
        for (int b = 0; b < 4; b++)
            #pragma unroll
            for (int c = 0; c < 4; c++) acc[a][b][c] = 0.0f;

    // --- main loop over 12 K-chunks ---
    for (int it = 0; it < KTILES; it++) {
        CP_WAIT2();
        __syncthreads();

        // issue stage it+3 into buffer (it-1)&3 (safe: sync above)
        int ld = it + NSTAGE - 1;
        if (ld < KTILES) {
            uint32_t smA = smbase + (ld & 3) * STAGE_BYTES;
            uint32_t smB = smA + 16384;
            const __nv_bfloat16* ga = Ag + ld * BKB + lq * 8;
            const __nv_bfloat16* gb = Bg + ld * BKB + lq * 8;
            #pragma unroll
            for (int i = 0; i < 4; i++) {
                uint32_t o = lo0 + (uint32_t)(i * 32 * 128);
                uint32_t sw = o ^ ((o >> 3) & 0x70);
                cp16(smA + sw, ga + (size_t)(lrow + 32 * i) * KSPLIT);
                cp16(smB + sw, gb + (size_t)(lrow + 32 * i) * KSPLIT);
            }
        }
        CP_COMMIT();

        uint32_t smA = smbase + (it & 3) * STAGE_BYTES;
        uint32_t smB = smA + 16384;

        #pragma unroll
        for (int ks = 0; ks < 4; ks++) {          // 4 x k16 per chunk
            uint32_t kb = (uint32_t)(ks * 32) + ksel;
            uint32_t a[4][4], b[2][4];
            #pragma unroll
            for (int tm = 0; tm < 4; tm++)
                ldsm4(a[tm], smA + arow[tm] + (kb ^ av[tm]));
            #pragma unroll
            for (int tg = 0; tg < 2; tg++)
                ldsm4(b[tg], smB + brow[tg] + (kb ^ bv[tg]));
            #pragma unroll
            for (int tm = 0; tm < 4; tm++) {
                mma16816(acc[tm][0], a[tm], b[0][0], b[0][2]);
                mma16816(acc[tm][1], a[tm], b[0][1], b[0][3]);
                mma16816(acc[tm][2], a[tm], b[1][0], b[1][2]);
                mma16816(acc[tm][3], a[tm], b[1][1], b[1][3]);
            }
        }
        __syncthreads();
    }

    // --- fused RBF epilogue: l2 = sqi + sqj - 2 dot, u = ex2(arg),
    //     ksum = u + u^2 + u^4 + u^8 + u^16 ---
    float twoc = -2.0f * negc;
    float tsum = 0.0f;
    #pragma unroll
    for (int tm = 0; tm < 4; tm++) {
        int mb = wm * 64 + tm * 16 + (lane >> 2);
        float si0 = sqic[mb], si8 = sqic[mb + 8];
        #pragma unroll
        for (int tn = 0; tn < 4; tn++) {
            int nb = wn * 32 + tn * 8 + (lane & 3) * 2;
            float sj0 = sqjc[nb], sj1 = sqjc[nb + 1];
            float* c = acc[tm][tn];
            float base[4] = { si0 + sj0, si0 + sj1, si8 + sj0, si8 + sj1 };
            #pragma unroll
            for (int e = 0; e < 4; e++) {
                float arg = fmaf(c[e], twoc, base[e]);
                float u = ex2f(arg);
                float u2 = u * u, u4 = u2 * u2, u8 = u4 * u4, u16 = u8 * u8;
                tsum += ((u + u2) + (u4 + u8)) + u16;
            }
        }
    }
    #pragma unroll
    for (int o = 16; o; o >>= 1) tsum += __shfl_xor_sync(0xffffffffu, tsum, o);
    if (lane == 0) redw[wid] = tsum;
    __syncthreads();
    if (tid == 0) {
        float s = ((redw[0] + redw[1]) + (redw[2] + redw[3]))
                + ((redw[4] + redw[5]) + (redw[6] + redw[7]));
        float w = ((i0 < HALF) == (j0 < HALF)) ? 1.0f : -1.0f;
        if (bi != bj) w *= 2.0f;          // triangle -> full matrix
        atomicAdd(&g_acc, (double)(s * w));
    }
}

// ---------------------------------------------------------------------------
// k4: finalize mean
// ---------------------------------------------------------------------------
__global__ void k4_final(float* out) {
    if (threadIdx.x == 0)
        out[0] = (float)(g_acc / ((double)HALF * (double)HALF));
}

extern "C" void kernel_launch(void* const* d_in, const int* in_sizes, int n_in,
                              void* d_out, int out_size) {
    const float* src = (const float*)d_in[0];
    const float* tgt = (const float*)d_in[1];
    float* out = (float*)d_out;

    cudaFuncSetAttribute(k3_mma, cudaFuncAttributeMaxDynamicSharedMemorySize, DSM_BYTES);

    k0_zero<<<1, 256>>>();
    k1_rowstats<<<NROWS / 8, 256>>>(src, tgt);
    k1b_convert<<<NROWS, 256>>>(src, tgt);
    k2_bandwidth<<<1, 256>>>();
    k3_mma<<<NTILES, 256, DSM_BYTES>>>();
    k4_final<<<1, 32>>>(out);
}